// round 16
// baseline (speedup 1.0000x reference)
#include <cuda_runtime.h>

// Problem constants
#define BSZ   4096
#define PSZ   32
#define EMB   128
#define HDIM  768
#define NBUCKET 256          // 16 batch rows per bucket
#define ARRIVALS 48          // 16 rows x 3 groups

// Scratch: intermediate H [B, 768] (12.6 MB)
__device__ float g_H[BSZ * HDIM];
// Bucket arrival counters (zero-init at load; winners self-reset -> graph-replay safe)
__device__ unsigned int g_cnt[NBUCKET];

__device__ __forceinline__ float4 relu_step(float4 x, float4 w, float4 y, float4 bm) {
    float4 r;
    r.x = fmaxf(fmaf(x.x * w.x, y.x, bm.x), 0.f);
    r.y = fmaxf(fmaf(x.y * w.y, y.y, bm.y), 0.f);
    r.z = fmaxf(fmaf(x.z * w.z, y.z, bm.z), 0.f);
    r.w = fmaxf(fmaf(x.w * w.w, y.w, bm.w), 0.f);
    return r;
}

struct PathPart {
    float sW[3 * EMB];
    float sB[3 * EMB];
    float sAcc[8][256];
    float sCnt[8];
};

#define HSTR 196
struct Smem {
    union {
        PathPart p;
        float    u[16 * HSTR];   // 3136 floats = 12.54 KB (mlp staging)
    };
    int winner;
};

// ── path phase: exact R4 logic ──────────────────────────────────────────
template<int L>
__device__ __forceinline__ void path_body(
    PathPart& sm,
    const int*   __restrict__ ents,
    const int*   __restrict__ mids,
    const float* __restrict__ counts,
    const float* __restrict__ E,
    const float* __restrict__ Wm,
    const float* __restrict__ Bm,
    int gofs)
{
    const int b    = blockIdx.x;
    const int tid  = threadIdx.x;
    const int wid  = tid >> 5;
    const int lane = tid & 31;

    for (int i = tid; i < 3 * EMB; i += 256) { sm.sW[i] = Wm[i]; sm.sB[i] = Bm[i]; }
    __syncthreads();

    int   e[4][L + 1];
    int   m[4][L];
    float cnt[4];
    #pragma unroll
    for (int pp = 0; pp < 4; pp++) {
        const long base = (long)b * PSZ + (wid + pp * 8);
        const int* ep = ents + base * (L + 1);
        const int* mp = mids + base * L;
        #pragma unroll
        for (int i = 0; i <= L; i++) e[pp][i] = ep[i];
        #pragma unroll
        for (int i = 0; i < L; i++)  m[pp][i] = mp[i];
        cnt[pp] = counts[base];
    }

    float4 a1 = make_float4(0.f, 0.f, 0.f, 0.f);
    float4 a2 = make_float4(0.f, 0.f, 0.f, 0.f);
    float  cs = 0.f;

    float4 buf[2][L + 1];
    #pragma unroll
    for (int i = 0; i <= L; i++)
        buf[0][i] = *(const float4*)(E + (long)e[0][i] * EMB + lane * 4);

    #pragma unroll
    for (int pp = 0; pp < 4; pp++) {
        if (pp < 3) {
            #pragma unroll
            for (int i = 0; i <= L; i++)
                buf[(pp + 1) & 1][i] =
                    *(const float4*)(E + (long)e[pp + 1][i] * EMB + lane * 4);
        }
        float4 (&rows)[L + 1] = buf[pp & 1];

        float4 x = rows[0];
        #pragma unroll
        for (int i = 0; i < L; i++) {
            float4 w  = *(const float4*)(sm.sW + m[pp][i] * EMB + lane * 4);
            float4 bb = *(const float4*)(sm.sB + m[pp][i] * EMB + lane * 4);
            x = relu_step(x, w, rows[i + 1], bb);
        }
        const float4 o1 = x;

        const float4 yl = rows[L];
        x = yl;
        #pragma unroll
        for (int i = L - 1; i >= 0; i--) {
            float4 w  = *(const float4*)(sm.sW + m[pp][i] * EMB + lane * 4);
            float4 bb = *(const float4*)(sm.sB + m[pp][i] * EMB + lane * 4);
            x = relu_step(x, w, yl, bb);
        }

        const float c0 = cnt[pp];
        a1.x += c0 * o1.x; a1.y += c0 * o1.y; a1.z += c0 * o1.z; a1.w += c0 * o1.w;
        a2.x += c0 * x.x;  a2.y += c0 * x.y;  a2.z += c0 * x.z;  a2.w += c0 * x.w;
        cs   += c0;
    }

    ((float4*)sm.sAcc[wid])[lane]         = a1;
    ((float4*)(sm.sAcc[wid] + 128))[lane] = a2;
    if (lane == 0) sm.sCnt[wid] = cs;
    __syncthreads();

    float s = 0.f, csum = 0.f;
    #pragma unroll
    for (int w = 0; w < 8; w++) { s += sm.sAcc[w][tid]; csum += sm.sCnt[w]; }
    g_H[(long)b * HDIM + gofs + tid] = s / csum;
}

// ── fused kernel: paths + last-arriver-runs-MLP ─────────────────────────
__global__ __launch_bounds__(256) void fused_kernel(
    const int* __restrict__ ent1, const int* __restrict__ mid1, const float* __restrict__ c1,
    const int* __restrict__ ent2, const int* __restrict__ mid2, const float* __restrict__ c2,
    const int* __restrict__ ent3, const int* __restrict__ mid3, const float* __restrict__ c3,
    const float* __restrict__ E, const float* __restrict__ Wm, const float* __restrict__ Bm,
    const float* __restrict__ W1, const float* __restrict__ b1,
    const float* __restrict__ W2, const float* __restrict__ b2,
    const float* __restrict__ W3, const float* __restrict__ b3,
    float* __restrict__ out)
{
    __shared__ Smem sm;
    const int tid = threadIdx.x;
    const int g   = blockIdx.y;

    // Path phase (writes 256 H entries for row blockIdx.x)
    if (g == 0)      path_body<1>(sm.p, ent1, mid1, c1, E, Wm, Bm, 0);
    else if (g == 1) path_body<2>(sm.p, ent2, mid2, c2, E, Wm, Bm, 256);
    else             path_body<3>(sm.p, ent3, mid3, c3, E, Wm, Bm, 512);

    // Release + arrive (threadFenceReduction idiom)
    __threadfence();
    __syncthreads();
    const int bucket = blockIdx.x >> 4;
    if (tid == 0) {
        const unsigned int old = atomicAdd(&g_cnt[bucket], 1u);
        sm.winner = (old == ARRIVALS - 1);
        if (old == ARRIVALS - 1) g_cnt[bucket] = 0u;   // self-reset for graph replay
    }
    __syncthreads();
    if (!sm.winner) return;

    // ── MLP for this bucket's 16 rows (runs while other path blocks fly) ─
    const int b0 = (blockIdx.x >> 4) << 4;
    const int c  = tid & 127;
    const int rh = (tid >> 7) * 8;       // rows rh..rh+7

    float acc[8];
    {
        const float bias = __ldg(b1 + c);
        #pragma unroll
        for (int r = 0; r < 8; r++) acc[r] = bias;
    }

    // Phase A: h1 = relu(H @ W1 + b1); K streamed in 4 chunks of 192 via smem
    for (int ch = 0; ch < 4; ch++) {
        __syncthreads();
        #pragma unroll
        for (int j = 0; j < 3; j++) {
            const int idx = tid + j * 256;         // 0..767 float4s
            const int row = idx / 48, c4 = idx % 48;
            const float4 v = __ldcg((const float4*)(g_H + (long)(b0 + row) * HDIM
                                                    + ch * 192 + c4 * 4));
            *(float4*)(sm.u + row * HSTR + c4 * 4) = v;
        }
        __syncthreads();
        #pragma unroll 4
        for (int kk = 0; kk < 192; kk += 4) {
            const float* wp = W1 + (ch * 192 + kk) * 128 + c;
            const float w0 = __ldg(wp);
            const float w1 = __ldg(wp + 128);
            const float w2 = __ldg(wp + 256);
            const float w3 = __ldg(wp + 384);
            #pragma unroll
            for (int r = 0; r < 8; r++) {
                const float4 h = *(const float4*)(sm.u + (rh + r) * HSTR + kk);
                float a = acc[r];
                a = fmaf(h.x, w0, a);
                a = fmaf(h.y, w1, a);
                a = fmaf(h.z, w2, a);
                a = fmaf(h.w, w3, a);
                acc[r] = a;
            }
        }
    }
    __syncthreads();

    float* const sh1 = sm.u;             // [16][132]
    float* const sh2 = sm.u + 16 * 132;  // [16][33]
    #pragma unroll
    for (int r = 0; r < 8; r++)
        sh1[(rh + r) * 132 + c] = fmaxf(acc[r], 0.f);
    __syncthreads();

    // Phase B: h2 = relu(h1 @ W2 + b2) — 256 thr = 16 rows × 16 col-pairs
    {
        const int r  = tid >> 4;             // 0..15
        const int cb = (tid & 15) * 2;       // 0,2,...,30
        float a0 = __ldg(b2 + cb), a1 = __ldg(b2 + cb + 1);
        #pragma unroll 8
        for (int k = 0; k < 128; k++) {
            const float  h = sh1[r * 132 + k];
            const float2 w = *(const float2*)(W2 + k * 32 + cb);
            a0 = fmaf(h, w.x, a0);
            a1 = fmaf(h, w.y, a1);
        }
        sh2[r * 33 + cb]     = fmaxf(a0, 0.f);
        sh2[r * 33 + cb + 1] = fmaxf(a1, 0.f);
    }
    __syncthreads();

    // Phase C: out = h2 @ W3 + b3
    if (tid < 16) {
        float a = __ldg(b3);
        #pragma unroll
        for (int k = 0; k < 32; k++) a = fmaf(sh2[tid * 33 + k], __ldg(W3 + k), a);
        out[b0 + tid] = a;
    }
}

extern "C" void kernel_launch(void* const* d_in, const int* in_sizes, int n_in,
                              void* d_out, int out_size)
{
    const bool dictOrder = (in_sizes[2] == BSZ * PSZ);

    const int *ent1, *mid1, *ent2, *mid2, *ent3, *mid3;
    const float *c1, *c2, *c3;
    if (dictOrder) {
        ent1 = (const int*)d_in[0]; mid1 = (const int*)d_in[1]; c1 = (const float*)d_in[2];
        ent2 = (const int*)d_in[3]; mid2 = (const int*)d_in[4]; c2 = (const float*)d_in[5];
        ent3 = (const int*)d_in[6]; mid3 = (const int*)d_in[7]; c3 = (const float*)d_in[8];
    } else {
        ent1 = (const int*)d_in[0]; mid1 = (const int*)d_in[1];
        ent2 = (const int*)d_in[2]; mid2 = (const int*)d_in[3];
        ent3 = (const int*)d_in[4]; mid3 = (const int*)d_in[5];
        c1 = (const float*)d_in[6]; c2 = (const float*)d_in[7]; c3 = (const float*)d_in[8];
    }
    const float* E  = (const float*)d_in[9];
    const float* Wm = (const float*)d_in[10];
    const float* Bm = (const float*)d_in[11];
    const float* W1 = (const float*)d_in[12];
    const float* b1 = (const float*)d_in[13];
    const float* W2 = (const float*)d_in[14];
    const float* b2 = (const float*)d_in[15];
    const float* W3 = (const float*)d_in[16];
    const float* b3 = (const float*)d_in[17];

    dim3 pgrid(BSZ, 3);
    fused_kernel<<<pgrid, 256>>>(ent1, mid1, c1, ent2, mid2, c2, ent3, mid3, c3,
                                 E, Wm, Bm, W1, b1, W2, b2, W3, b3, (float*)d_out);
}

// round 17
// speedup vs baseline: 1.1080x; 1.1080x over previous
#include <cuda_runtime.h>

// Problem constants
#define BSZ   4096
#define PSZ   32
#define EMB   128
#define HDIM  768
#define MROWS 16            // batch rows per MLP block

// Scratch: intermediate H [B, 768] (12.6 MB)
__device__ float g_H[BSZ * HDIM];

__device__ __forceinline__ float4 relu_step(float4 x, float4 w, float4 y, float4 bm) {
    float4 r;
    r.x = fmaxf(fmaf(x.x * w.x, y.x, bm.x), 0.f);
    r.y = fmaxf(fmaf(x.y * w.y, y.y, bm.y), 0.f);
    r.z = fmaxf(fmaf(x.z * w.z, y.z, bm.z), 0.f);
    r.w = fmaxf(fmaf(x.w * w.w, y.w, bm.w), 0.f);
    return r;
}

struct PathSmem {
    float sW[3 * EMB];
    float sB[3 * EMB];
    float sAcc[8][256];
    float sCnt[8];
};

// One GROUP body for batch row blockIdx.x — exact R4 logic, minus the
// sW/sB staging (done once by the caller). 8 warps; warp w handles paths
// p = w, w+8, w+16, w+24 with 1-path lookahead prefetch of embedding rows.
template<int L>
__device__ __forceinline__ void path_group(
    PathSmem& sm,
    const int*   __restrict__ ents,    // [B,P,L+1]
    const int*   __restrict__ mids,    // [B,P,L]
    const float* __restrict__ counts,  // [B,P]
    const float* __restrict__ E,       // [100000,128]
    int gofs)
{
    const int b    = blockIdx.x;
    const int tid  = threadIdx.x;
    const int wid  = tid >> 5;
    const int lane = tid & 31;

    int   e[4][L + 1];
    int   m[4][L];
    float cnt[4];
    #pragma unroll
    for (int pp = 0; pp < 4; pp++) {
        const long base = (long)b * PSZ + (wid + pp * 8);
        const int* ep = ents + base * (L + 1);
        const int* mp = mids + base * L;
        #pragma unroll
        for (int i = 0; i <= L; i++) e[pp][i] = ep[i];
        #pragma unroll
        for (int i = 0; i < L; i++)  m[pp][i] = mp[i];
        cnt[pp] = counts[base];
    }

    float4 a1 = make_float4(0.f, 0.f, 0.f, 0.f);
    float4 a2 = make_float4(0.f, 0.f, 0.f, 0.f);
    float  cs = 0.f;

    float4 buf[2][L + 1];
    #pragma unroll
    for (int i = 0; i <= L; i++)
        buf[0][i] = *(const float4*)(E + (long)e[0][i] * EMB + lane * 4);

    #pragma unroll
    for (int pp = 0; pp < 4; pp++) {
        if (pp < 3) {
            #pragma unroll
            for (int i = 0; i <= L; i++)
                buf[(pp + 1) & 1][i] =
                    *(const float4*)(E + (long)e[pp + 1][i] * EMB + lane * 4);
        }
        float4 (&rows)[L + 1] = buf[pp & 1];

        // forward
        float4 x = rows[0];
        #pragma unroll
        for (int i = 0; i < L; i++) {
            float4 w  = *(const float4*)(sm.sW + m[pp][i] * EMB + lane * 4);
            float4 bb = *(const float4*)(sm.sB + m[pp][i] * EMB + lane * 4);
            x = relu_step(x, w, rows[i + 1], bb);
        }
        const float4 o1 = x;

        // backward: start x and (stale) y are both E[ents[L]]
        const float4 yl = rows[L];
        x = yl;
        #pragma unroll
        for (int i = L - 1; i >= 0; i--) {
            float4 w  = *(const float4*)(sm.sW + m[pp][i] * EMB + lane * 4);
            float4 bb = *(const float4*)(sm.sB + m[pp][i] * EMB + lane * 4);
            x = relu_step(x, w, yl, bb);
        }

        const float c0 = cnt[pp];
        a1.x += c0 * o1.x; a1.y += c0 * o1.y; a1.z += c0 * o1.z; a1.w += c0 * o1.w;
        a2.x += c0 * x.x;  a2.y += c0 * x.y;  a2.z += c0 * x.z;  a2.w += c0 * x.w;
        cs   += c0;
    }

    ((float4*)sm.sAcc[wid])[lane]         = a1;   // dims 0..127
    ((float4*)(sm.sAcc[wid] + 128))[lane] = a2;   // dims 128..255
    if (lane == 0) sm.sCnt[wid] = cs;
    __syncthreads();

    float s = 0.f, csum = 0.f;
    #pragma unroll
    for (int w = 0; w < 8; w++) { s += sm.sAcc[w][tid]; csum += sm.sCnt[w]; }
    g_H[(long)b * HDIM + gofs + tid] = s / csum;

    __syncthreads();   // protect sAcc reuse by the next group
}

// One block per batch row; runs all 3 groups sequentially.
__global__ __launch_bounds__(256) void paths_kernel(
    const int* __restrict__ ent1, const int* __restrict__ mid1, const float* __restrict__ c1,
    const int* __restrict__ ent2, const int* __restrict__ mid2, const float* __restrict__ c2,
    const int* __restrict__ ent3, const int* __restrict__ mid3, const float* __restrict__ c3,
    const float* __restrict__ E, const float* __restrict__ Wm, const float* __restrict__ Bm)
{
    __shared__ PathSmem sm;
    const int tid = threadIdx.x;

    for (int i = tid; i < 3 * EMB; i += 256) { sm.sW[i] = Wm[i]; sm.sB[i] = Bm[i]; }
    __syncthreads();

    path_group<1>(sm, ent1, mid1, c1, E, 0);
    path_group<2>(sm, ent2, mid2, c2, E, 256);
    path_group<3>(sm, ent3, mid3, c3, E, 512);
}

// ────────────────────────────────────────────────────────────────────────
// MLP head (R4 plain-fp32 — best by end-to-end timing):
// 16 rows/block, 512 threads, 256 blocks.
// ────────────────────────────────────────────────────────────────────────
__global__ __launch_bounds__(512) void mlp_kernel(
    const float* __restrict__ W1, const float* __restrict__ b1,
    const float* __restrict__ W2, const float* __restrict__ b2,
    const float* __restrict__ W3, const float* __restrict__ b3,
    float* __restrict__ out)
{
    __shared__ float smem[MROWS * HDIM];        // 48 KB
    float* const sH = smem;

    const int b0  = blockIdx.x * MROWS;
    const int tid = threadIdx.x;

    // Load full H tile (3072 float4, 6 per thread)
    {
        const float4* src = (const float4*)(g_H + (long)b0 * HDIM);
        float4*       dst = (float4*)sH;
        #pragma unroll
        for (int i = 0; i < (MROWS * HDIM / 4) / 512; i++)
            dst[tid + i * 512] = src[tid + i * 512];
    }
    __syncthreads();

    // ── Phase A: h1 = relu(H @ W1 + b1), [16,128] ────────────────────────
    const int c     = tid & 127;
    const int rbase = (tid >> 7) * 4;     // 0,4,8,12
    float acc[4];
    {
        const float bias1 = b1[c];
        #pragma unroll
        for (int r = 0; r < 4; r++) acc[r] = bias1;
    }

    #pragma unroll 4
    for (int kb = 0; kb < HDIM; kb += 4) {
        const float* wp = W1 + kb * 128 + c;
        const float w0 = __ldg(wp);
        const float w1 = __ldg(wp + 128);
        const float w2 = __ldg(wp + 256);
        const float w3 = __ldg(wp + 384);
        #pragma unroll
        for (int r = 0; r < 4; r++) {
            const float4 h = *(const float4*)(sH + (rbase + r) * HDIM + kb);
            float a = acc[r];
            a = fmaf(h.x, w0, a);
            a = fmaf(h.y, w1, a);
            a = fmaf(h.z, w2, a);
            a = fmaf(h.w, w3, a);
            acc[r] = a;
        }
    }
    __syncthreads();          // everyone done reading sH

    float* const sh1 = smem;                 // [16][128]
    float* const sh2 = smem + MROWS * 128;   // [16][32]
    #pragma unroll
    for (int r = 0; r < 4; r++)
        sh1[(rbase + r) * 128 + c] = fmaxf(acc[r], 0.f);
    __syncthreads();

    // ── Phase B: h2 = relu(h1 @ W2 + b2), [16,32] — 512 thr = 16r × 32c ──
    {
        const int c2 = tid & 31;
        const int r  = tid >> 5;   // 0..15
        float a = b2[c2];
        #pragma unroll 8
        for (int k = 0; k < 128; k += 4) {
            const float4 h = *(const float4*)(sh1 + r * 128 + k);
            a = fmaf(h.x, __ldg(W2 + (k    ) * 32 + c2), a);
            a = fmaf(h.y, __ldg(W2 + (k + 1) * 32 + c2), a);
            a = fmaf(h.z, __ldg(W2 + (k + 2) * 32 + c2), a);
            a = fmaf(h.w, __ldg(W2 + (k + 3) * 32 + c2), a);
        }
        sh2[r * 32 + c2] = fmaxf(a, 0.f);
    }
    __syncthreads();

    // ── Phase C: out = h2 @ W3 + b3, [16,1] ─────────────────────────────
    if (tid < MROWS) {
        float a = b3[0];
        #pragma unroll
        for (int k = 0; k < 32; k++) a = fmaf(sh2[tid * 32 + k], W3[k], a);
        out[b0 + tid] = a;
    }
}

extern "C" void kernel_launch(void* const* d_in, const int* in_sizes, int n_in,
                              void* d_out, int out_size)
{
    const bool dictOrder = (in_sizes[2] == BSZ * PSZ);

    const int *ent1, *mid1, *ent2, *mid2, *ent3, *mid3;
    const float *c1, *c2, *c3;
    if (dictOrder) {
        ent1 = (const int*)d_in[0]; mid1 = (const int*)d_in[1]; c1 = (const float*)d_in[2];
        ent2 = (const int*)d_in[3]; mid2 = (const int*)d_in[4]; c2 = (const float*)d_in[5];
        ent3 = (const int*)d_in[6]; mid3 = (const int*)d_in[7]; c3 = (const float*)d_in[8];
    } else {
        ent1 = (const int*)d_in[0]; mid1 = (const int*)d_in[1];
        ent2 = (const int*)d_in[2]; mid2 = (const int*)d_in[3];
        ent3 = (const int*)d_in[4]; mid3 = (const int*)d_in[5];
        c1 = (const float*)d_in[6]; c2 = (const float*)d_in[7]; c3 = (const float*)d_in[8];
    }
    const float* E  = (const float*)d_in[9];
    const float* Wm = (const float*)d_in[10];
    const float* Bm = (const float*)d_in[11];
    const float* W1 = (const float*)d_in[12];
    const float* b1 = (const float*)d_in[13];
    const float* W2 = (const float*)d_in[14];
    const float* b2 = (const float*)d_in[15];
    const float* W3 = (const float*)d_in[16];
    const float* b3 = (const float*)d_in[17];

    paths_kernel<<<BSZ, 256>>>(ent1, mid1, c1, ent2, mid2, c2, ent3, mid3, c3,
                               E, Wm, Bm);
    mlp_kernel<<<BSZ / MROWS, 512>>>(W1, b1, W2, b2, W3, b3, (float*)d_out);
}